// round 14
// baseline (speedup 1.0000x reference)
#include <cuda_runtime.h>
#include <math.h>
#include <stdint.h>

#define BATCH 128
#define SEQ   512
#define DIM   768
#define NCLS  9
#define ROWS  (BATCH * SEQ)   // 65536
#define D4    (DIM / 4)       // 192
#define NCHUNK 64             // CRF: 8 steps per chunk

// ---- gemm kernel constants ----
#define TILE_ROWS 32
#define TILE_BYTES (TILE_ROWS * DIM * 4)   // 98304
#define NTILES (ROWS / TILE_ROWS)          // 2048
#define NBLK 148
// dynamic smem layout
#define GOFF_W    0                        // 27648
#define GOFF_B    27648                    // 64
#define GOFF_MB   27712                    // 16 (2 mbarriers)
#define GOFF_T    28672                    // 2 * 98304
#define SMEM_G    (GOFF_T + 2 * TILE_BYTES)   // 225280

__device__ float g_llh[BATCH];
__device__ int   g_done;      // zero-init; self-resets (graph-replay safe)

// ---------------------------------------------------------------------------
// helpers
// ---------------------------------------------------------------------------
__device__ __forceinline__ uint32_t smem_u32(const void* p) {
    uint32_t a;
    asm("{ .reg .u64 t; cvta.to.shared.u64 t, %1; cvt.u32.u64 %0, t; }"
        : "=r"(a) : "l"(p));
    return a;
}
__device__ __forceinline__ void mbar_init(uint32_t addr, uint32_t count) {
    asm volatile("mbarrier.init.shared.b64 [%0], %1;" :: "r"(addr), "r"(count) : "memory");
}
__device__ __forceinline__ void mbar_expect_tx(uint32_t addr, uint32_t bytes) {
    asm volatile("mbarrier.arrive.expect_tx.shared.b64 _, [%0], %1;"
                 :: "r"(addr), "r"(bytes) : "memory");
}
__device__ __forceinline__ void mbar_wait(uint32_t addr, uint32_t parity) {
    asm volatile(
        "{\n\t.reg .pred P;\n\t"
        "WAITLP_%=:\n\t"
        "mbarrier.try_wait.parity.acquire.cta.shared::cta.b64 P, [%0], %1, 0x989680;\n\t"
        "@P bra.uni WDONE_%=;\n\t"
        "bra.uni WAITLP_%=;\n\t"
        "WDONE_%=:\n\t}"
        :: "r"(addr), "r"(parity) : "memory");
}
__device__ __forceinline__ void bulk_g2s(uint32_t dst, const void* src,
                                         uint32_t bytes, uint32_t mbar) {
    asm volatile(
        "cp.async.bulk.shared::cta.global.mbarrier::complete_tx::bytes [%0], [%1], %2, [%3];"
        :: "r"(dst), "l"(src), "r"(bytes), "r"(mbar) : "memory");
}
__device__ __forceinline__ void fence_proxy_async_s() {
    asm volatile("fence.proxy.async.shared::cta;" ::: "memory");
}

// ---------------------------------------------------------------------------
// Kernel 1: persistent TMA-fed GEMM. 148 blocks x 256 threads, 1 block/SM.
// Two 96KB stages (32 rows each) filled by cp.async.bulk; 8 warps each own
// 4 complete rows per tile (group = 1 row, 8-lane D-split, W broadcast LDS),
// so consumption needs no cross-warp reduction. Arithmetic chain identical
// to R8's gemm -> bit-identical logits.
// ---------------------------------------------------------------------------
__global__ __launch_bounds__(256, 1) void gemm_kernel(
    const float* __restrict__ feat,
    const float* __restrict__ W,
    const float* __restrict__ bias,
    float*       __restrict__ out_logits)
{
    extern __shared__ char smem[];
    float4* Ws4  = (float4*)(smem + GOFF_W);
    float*  bS   = (float*)(smem + GOFF_B);
    const uint32_t mb = smem_u32(smem + GOFF_MB);
    char*   tiles = smem + GOFF_T;

    const int tid  = threadIdx.x;
    const int warp = tid >> 5;
    const int lane = tid & 31;
    const int li   = lane & 7;   // d-chunk within group
    const int g    = lane >> 3;  // group (0..3), 1 row each

    const float4* W4 = (const float4*)W;
    for (int i = tid; i < NCLS * D4; i += 256) Ws4[i] = W4[i];
    if (tid < NCLS) bS[tid] = bias[tid];
    if (tid == 0) {
        mbar_init(mb, 1);
        mbar_init(mb + 8, 1);
        fence_proxy_async_s();
    }
    __syncthreads();

    const int nt = (NTILES - blockIdx.x + (NBLK - 1)) / NBLK;

    if (tid == 0) {
#pragma unroll
        for (int j = 0; j < 2; ++j) {
            if (j < nt) {
                const int t = blockIdx.x + j * NBLK;
                mbar_expect_tx(mb + 8 * j, TILE_BYTES);
                bulk_g2s(smem_u32(tiles + j * TILE_BYTES),
                         feat + (size_t)t * TILE_ROWS * DIM, TILE_BYTES, mb + 8 * j);
            }
        }
    }

    const int rloc = warp * 4 + g;     // local row 0..31

    for (int it = 0; it < nt; ++it) {
        const int s = it & 1;
        mbar_wait(mb + 8 * s, (it >> 1) & 1);

        const float4* fa = (const float4*)(tiles + s * TILE_BYTES + rloc * (DIM * 4));

        float acc[NCLS];
#pragma unroll
        for (int n = 0; n < NCLS; ++n) acc[n] = 0.f;

#pragma unroll 4
        for (int k = 0; k < 24; ++k) {
            const int idx = k * 8 + li;          // 0..191
            const float4 a = fa[idx];
#pragma unroll
            for (int n = 0; n < NCLS; ++n) {
                const float4 w = Ws4[n * D4 + idx];
                acc[n] = fmaf(a.x, w.x, fmaf(a.y, w.y, fmaf(a.z, w.z, fmaf(a.w, w.w, acc[n]))));
            }
        }

#pragma unroll
        for (int n = 0; n < NCLS; ++n) {
#pragma unroll
            for (int off = 4; off; off >>= 1)
                acc[n] += __shfl_down_sync(0xffffffffu, acc[n], off, 8);
        }

        if (li == 0) {
            const size_t grow = (size_t)(blockIdx.x + it * NBLK) * TILE_ROWS + rloc;
#pragma unroll
            for (int n = 0; n < NCLS; ++n)
                out_logits[grow * NCLS + n] = acc[n] + bS[n];
        }

        __syncthreads();   // all warps finished reading stage s

        if (tid == 0 && it + 2 < nt) {
            const int t = blockIdx.x + (it + 2) * NBLK;
            fence_proxy_async_s();
            mbar_expect_tx(mb + 8 * s, TILE_BYTES);
            bulk_g2s(smem_u32(tiles + s * TILE_BYTES),
                     feat + (size_t)t * TILE_ROWS * DIM, TILE_BYTES, mb + 8 * s);
        }
    }
}

// ---------------------------------------------------------------------------
// Kernel 2: CRF NLL per batch + fused final reduction (R11, 512 threads).
// ---------------------------------------------------------------------------
__global__ __launch_bounds__(512) void crf_kernel(
    const float* __restrict__ logits,
    const int*   __restrict__ labels,
    const int*   __restrict__ mask,
    const float* __restrict__ start_t,
    const float* __restrict__ end_t,
    const float* __restrict__ trans,
    float*       __restrict__ out)
{
    __shared__ float EE[SEQ * NCLS];          // 18432 B
    __shared__ float B8[NCHUNK * 81];         // 20736 B
    __shared__ float trT[NCLS * 12];
    __shared__ float trS[NCLS * NCLS];
    __shared__ int   tagS[SEQ];
    __shared__ int   mS[SEQ + 1];
    __shared__ float stS[NCLS], enS[NCLS];
    __shared__ float num_sh, den_sh;
    __shared__ int   isLast;
    __shared__ float ws[4];

    const int b   = blockIdx.x;
    const int tid = threadIdx.x;
    const float* lgb = logits + (size_t)b * SEQ * NCLS;

    // ---- Phase A ----
    for (int i = tid; i < SEQ * NCLS; i += 512)
        EE[i] = __expf(lgb[i]);
    for (int i = tid; i < SEQ; i += 512) {
        const int lab = labels[(size_t)b * SEQ + i];
        tagS[i] = (lab == -100) ? 0 : lab;
        mS[i]   = (mask[(size_t)b * SEQ + i] != 0) ? 1 : 0;
    }
    if (tid == 0) mS[SEQ] = 0;
    if (tid < NCLS * NCLS) {
        const float tv = trans[tid];
        trS[tid] = tv;
        const int i = tid / NCLS, k = tid % NCLS;
        trT[k * 12 + i] = __expf(tv);
    }
    if (tid < NCLS) { stS[tid] = start_t[tid]; enS[tid] = end_t[tid]; }
    __syncthreads();

    // ---- Phase B ----
    for (int task = tid; task < NCHUNK * NCLS; task += 512) {
        const int c = task / NCLS;
        const int j = task - c * NCLS;
        float v[NCLS];
#pragma unroll
        for (int i = 0; i < NCLS; ++i) v[i] = (i == j) ? 1.f : 0.f;

#pragma unroll
        for (int s = 7; s >= 0; --s) {
            const int t = 8 * c + 1 + s;
            if (mS[t]) {
                const float* eT = &EE[t * NCLS];
                float4 va = make_float4(0.f, 0.f, 0.f, 0.f);
                float4 vb = make_float4(0.f, 0.f, 0.f, 0.f);
                float  v8 = 0.f;
#pragma unroll
                for (int k = 0; k < NCLS; ++k) {
                    const float u = eT[k] * v[k];
                    const float4 t0 = *reinterpret_cast<const float4*>(trT + k * 12 + 0);
                    const float4 t1 = *reinterpret_cast<const float4*>(trT + k * 12 + 4);
                    const float  t2 = trT[k * 12 + 8];
                    va.x = fmaf(t0.x, u, va.x); va.y = fmaf(t0.y, u, va.y);
                    va.z = fmaf(t0.z, u, va.z); va.w = fmaf(t0.w, u, va.w);
                    vb.x = fmaf(t1.x, u, vb.x); vb.y = fmaf(t1.y, u, vb.y);
                    vb.z = fmaf(t1.z, u, vb.z); vb.w = fmaf(t1.w, u, vb.w);
                    v8   = fmaf(t2,   u, v8);
                }
                v[0] = va.x; v[1] = va.y; v[2] = va.z; v[3] = va.w;
                v[4] = vb.x; v[5] = vb.y; v[6] = vb.z; v[7] = vb.w;
                v[8] = v8;
            }
        }
#pragma unroll
        for (int i = 0; i < NCLS; ++i)
            B8[c * 81 + i * NCLS + j] = v[i];
    }
    __syncthreads();

    // ---- Phase C ----
    const int warp = tid >> 5;
    const int lane = tid & 31;

    if (warp == 0) {
        const int j = (lane < NCLS) ? lane : 0;
        float p = (lane < NCLS) ? __expf(stS[j] + lgb[j]) : 0.f;
        float clog = 0.f;

        float bcol[NCLS];
#pragma unroll
        for (int i = 0; i < NCLS; ++i) bcol[i] = B8[i * NCLS + j];

        for (int ch = 0; ch < NCHUNK; ++ch) {
            float nb[NCLS];
            if (ch < NCHUNK - 1) {
                const float* base = B8 + (ch + 1) * 81 + j;
#pragma unroll
                for (int i = 0; i < NCLS; ++i) nb[i] = base[i * NCLS];
            }

            const float p0 = __shfl_sync(0xffffffffu, p, 0);
            const float p1 = __shfl_sync(0xffffffffu, p, 1);
            const float p2 = __shfl_sync(0xffffffffu, p, 2);
            const float p3 = __shfl_sync(0xffffffffu, p, 3);
            const float p4 = __shfl_sync(0xffffffffu, p, 4);
            const float p5 = __shfl_sync(0xffffffffu, p, 5);
            const float p6 = __shfl_sync(0xffffffffu, p, 6);
            const float p7 = __shfl_sync(0xffffffffu, p, 7);
            const float p8 = __shfl_sync(0xffffffffu, p, 8);

            const float s0 = fmaf(p2, bcol[2], fmaf(p1, bcol[1], p0 * bcol[0]));
            const float s1 = fmaf(p5, bcol[5], fmaf(p4, bcol[4], p3 * bcol[3]));
            const float s2 = fmaf(p8, bcol[8], fmaf(p7, bcol[7], p6 * bcol[6]));
            float pn = (s0 + s1) + s2;

            if (ch & 1) {
                const float sv = __shfl_sync(0xffffffffu, pn, 0);
                pn *= __frcp_rn(sv);
                clog += __logf(sv);
            }
            p = pn;
#pragma unroll
            for (int i = 0; i < NCLS; ++i) bcol[i] = nb[i];
        }

        float v = (lane < NCLS) ? p * __expf(enS[j]) : 0.f;
#pragma unroll
        for (int off = 16; off; off >>= 1)
            v += __shfl_xor_sync(0xffffffffu, v, off);
        if (lane == 0) den_sh = clog + __logf(v);
    }
    else if (warp == 1) {
        float sc = 0.f;
        int   cnt = 0;
        for (int t = lane; t < SEQ; t += 32) {
            const int mt = mS[t];
            cnt += mt;
            if (t >= 1 && mt) {
                const int cur = tagS[t];
                const int prv = tagS[t - 1];
                sc += lgb[t * NCLS + cur] + trS[prv * NCLS + cur];
            }
        }
#pragma unroll
        for (int off = 16; off; off >>= 1) {
            sc  += __shfl_xor_sync(0xffffffffu, sc,  off);
            cnt += __shfl_xor_sync(0xffffffffu, cnt, off);
        }
        if (lane == 0) {
            const int first = tagS[0];
            sc += stS[first] + lgb[first];
            sc += enS[tagS[cnt - 1]];
            num_sh = sc;
        }
    }

    __syncthreads();

    // ---- Phase D ----
    if (tid == 0) {
        g_llh[b] = num_sh - den_sh;
        __threadfence();
        const int old = atomicAdd(&g_done, 1);
        isLast = (old == BATCH - 1) ? 1 : 0;
    }
    __syncthreads();

    if (isLast) {
        if (tid < 128) {
            float v = g_llh[tid];
#pragma unroll
            for (int off = 16; off; off >>= 1)
                v += __shfl_xor_sync(0xffffffffu, v, off);
            if (lane == 0) ws[warp] = v;
        }
        __syncthreads();
        if (tid == 0) {
            const float tot = (ws[0] + ws[1]) + (ws[2] + ws[3]);
            out[0] = -tot / (float)BATCH;
            g_done = 0;
        }
    }
}

extern "C" void kernel_launch(void* const* d_in, const int* in_sizes, int n_in,
                              void* d_out, int out_size)
{
    const float* feat   = (const float*)d_in[0];
    const int*   labels = (const int*)d_in[1];
    const int*   mask   = (const int*)d_in[2];
    const float* W      = (const float*)d_in[3];
    const float* bias   = (const float*)d_in[4];
    const float* st     = (const float*)d_in[5];
    const float* en     = (const float*)d_in[6];
    const float* tr     = (const float*)d_in[7];

    float* out    = (float*)d_out;
    float* logits = out + 1;

    static int configured = 0;
    if (!configured) {
        cudaFuncSetAttribute(gemm_kernel,
                             cudaFuncAttributeMaxDynamicSharedMemorySize, SMEM_G);
        configured = 1;
    }

    gemm_kernel<<<NBLK, 256, SMEM_G>>>(feat, W, bias, logits);
    crf_kernel<<<BATCH, 512>>>(logits, labels, mask, st, en, tr, out);
}

// round 15
// speedup vs baseline: 1.3845x; 1.3845x over previous
#include <cuda_runtime.h>
#include <math.h>
#include <stdint.h>

#define BATCH 128
#define SEQ   512
#define DIM   768
#define NCLS  9
#define ROWS  (BATCH * SEQ)   // 65536
#define D4    (DIM / 4)       // 192
#define NCHUNK 64             // 8 steps per chunk, covers t=1..512 (t=512 padded)

__device__ float g_llh[BATCH];
__device__ int   g_done;      // zero-init; self-resets each run (graph-replay safe)

// ---------------------------------------------------------------------------
// Kernel 1: logits = features @ W^T + b   (R8-proven structure, verbatim
// arithmetic; only load policy changed to streaming/evict-first).
// 256 threads, 4 blocks/SM (32 warps). Warp = 8 rows: 4 groups x 2 rows,
// 8 lanes/group split D into float4 chunks. W in smem, group-broadcast LDS.
// ---------------------------------------------------------------------------
__global__ __launch_bounds__(256, 4) void gemm_kernel(
    const float4* __restrict__ feat4,
    const float*  __restrict__ W,
    const float*  __restrict__ bias,
    float*        __restrict__ out_logits)
{
    __shared__ float4 Ws4[NCLS * D4];  // 27648 B
    __shared__ float  bS[NCLS];

    const float4* W4 = reinterpret_cast<const float4*>(W);
    for (int i = threadIdx.x; i < NCLS * D4; i += 256) Ws4[i] = W4[i];
    if (threadIdx.x < NCLS) bS[threadIdx.x] = bias[threadIdx.x];
    __syncthreads();

    const int warp = threadIdx.x >> 5;
    const int lane = threadIdx.x & 31;
    const int li   = lane & 7;   // d-chunk within group
    const int g    = lane >> 3;  // group (0..3), 2 rows each

    const int rowa = blockIdx.x * 64 + warp * 8 + g * 2;
    const int rowb = rowa + 1;

    float acc[NCLS][2];
#pragma unroll
    for (int n = 0; n < NCLS; ++n) { acc[n][0] = 0.f; acc[n][1] = 0.f; }

    const float4* fa = feat4 + (size_t)rowa * D4;
    const float4* fb = feat4 + (size_t)rowb * D4;

#pragma unroll 2
    for (int k = 0; k < 24; ++k) {
        const int idx = k * 8 + li;          // 0..191
        const float4 a  = __ldcs(fa + idx);  // streaming: no reuse, evict-first
        const float4 bv = __ldcs(fb + idx);
#pragma unroll
        for (int n = 0; n < NCLS; ++n) {
            const float4 w = Ws4[n * D4 + idx];
            acc[n][0] = fmaf(a.x,  w.x, fmaf(a.y,  w.y, fmaf(a.z,  w.z, fmaf(a.w,  w.w, acc[n][0]))));
            acc[n][1] = fmaf(bv.x, w.x, fmaf(bv.y, w.y, fmaf(bv.z, w.z, fmaf(bv.w, w.w, acc[n][1]))));
        }
    }

    // reduce over the 8 lanes of each group
#pragma unroll
    for (int n = 0; n < NCLS; ++n) {
#pragma unroll
        for (int off = 4; off; off >>= 1) {
            acc[n][0] += __shfl_down_sync(0xffffffffu, acc[n][0], off, 8);
            acc[n][1] += __shfl_down_sync(0xffffffffu, acc[n][1], off, 8);
        }
    }

    if (li == 0) {
#pragma unroll
        for (int n = 0; n < NCLS; ++n) {
            out_logits[(size_t)rowa * NCLS + n] = acc[n][0] + bS[n];
            out_logits[(size_t)rowb * NCLS + n] = acc[n][1] + bS[n];
        }
    }
}

// ---------------------------------------------------------------------------
// Kernel 2: CRF NLL per batch + fused final reduction.
// 768 threads (24 warps): Phase B's 576 column tasks fit in ONE pass and
// occupancy rises to 37.5% (vs 25% @512), while the measured 82-reg budget
// still fits (64K/768 = 85 regs/thread).
// ---------------------------------------------------------------------------
__global__ __launch_bounds__(768) void crf_kernel(
    const float* __restrict__ logits,
    const int*   __restrict__ labels,
    const int*   __restrict__ mask,
    const float* __restrict__ start_t,
    const float* __restrict__ end_t,
    const float* __restrict__ trans,
    float*       __restrict__ out)
{
    __shared__ float EE[SEQ * NCLS];          // 18432 B  exp(logits)
    __shared__ float B8[NCHUNK * 81];         // 20736 B  transfer matrices [c][i][j]
    __shared__ float trT[NCLS * 12];          // exp(trans) transposed, padded rows
    __shared__ float trS[NCLS * NCLS];        // raw trans (numerator)
    __shared__ int   tagS[SEQ];
    __shared__ int   mS[SEQ + 1];
    __shared__ float stS[NCLS], enS[NCLS];
    __shared__ float num_sh, den_sh;
    __shared__ int   isLast;
    __shared__ float ws[4];

    const int b   = blockIdx.x;
    const int tid = threadIdx.x;
    const float* lgb = logits + (size_t)b * SEQ * NCLS;

    // ---- Phase A: staging ----
    for (int i = tid; i < SEQ * NCLS; i += 768)
        EE[i] = __expf(lgb[i]);
    for (int i = tid; i < SEQ; i += 768) {
        const int lab = labels[(size_t)b * SEQ + i];
        tagS[i] = (lab == -100) ? 0 : lab;
        mS[i]   = (mask[(size_t)b * SEQ + i] != 0) ? 1 : 0;
    }
    if (tid == 0) mS[SEQ] = 0;                // pad step t=512
    if (tid < NCLS * NCLS) {
        const float tv = trans[tid];
        trS[tid] = tv;
        const int i = tid / NCLS, k = tid % NCLS;
        trT[k * 12 + i] = __expf(tv);         // trT[k][i] = exp(trans[i][k])
    }
    if (tid < NCLS) { stS[tid] = start_t[tid]; enS[tid] = end_t[tid]; }
    __syncthreads();

    // ---- Phase B: build B8 (576 column tasks, single pass over 768 thr) ----
    if (tid < NCHUNK * NCLS) {
        const int c = tid / NCLS;
        const int j = tid - c * NCLS;
        float v[NCLS];
#pragma unroll
        for (int i = 0; i < NCLS; ++i) v[i] = (i == j) ? 1.f : 0.f;

        // right-to-left: v = A_{t1} (... (A_{t8} e_j))
#pragma unroll
        for (int s = 7; s >= 0; --s) {
            const int t = 8 * c + 1 + s;       // 1..512
            if (mS[t]) {
                const float* eT = &EE[t * NCLS];
                float4 va = make_float4(0.f, 0.f, 0.f, 0.f);
                float4 vb = make_float4(0.f, 0.f, 0.f, 0.f);
                float  v8 = 0.f;
#pragma unroll
                for (int k = 0; k < NCLS; ++k) {
                    const float u = eT[k] * v[k];
                    const float4 t0 = *reinterpret_cast<const float4*>(trT + k * 12 + 0);
                    const float4 t1 = *reinterpret_cast<const float4*>(trT + k * 12 + 4);
                    const float  t2 = trT[k * 12 + 8];
                    va.x = fmaf(t0.x, u, va.x); va.y = fmaf(t0.y, u, va.y);
                    va.z = fmaf(t0.z, u, va.z); va.w = fmaf(t0.w, u, va.w);
                    vb.x = fmaf(t1.x, u, vb.x); vb.y = fmaf(t1.y, u, vb.y);
                    vb.z = fmaf(t1.z, u, vb.z); vb.w = fmaf(t1.w, u, vb.w);
                    v8   = fmaf(t2,   u, v8);
                }
                v[0] = va.x; v[1] = va.y; v[2] = va.z; v[3] = va.w;
                v[4] = vb.x; v[5] = vb.y; v[6] = vb.z; v[7] = vb.w;
                v[8] = v8;
            }
        }
#pragma unroll
        for (int i = 0; i < NCLS; ++i)
            B8[c * 81 + i * NCLS + j] = v[i];
    }
    __syncthreads();

    // ---- Phase C ----
    const int warp = tid >> 5;
    const int lane = tid & 31;

    if (warp == 0) {
        const int j = (lane < NCLS) ? lane : 0;
        float p = (lane < NCLS) ? __expf(stS[j] + lgb[j]) : 0.f;
        float clog = 0.f;

        float bcol[NCLS];
#pragma unroll
        for (int i = 0; i < NCLS; ++i) bcol[i] = B8[i * NCLS + j];

        for (int ch = 0; ch < NCHUNK; ++ch) {
            float nb[NCLS];
            if (ch < NCHUNK - 1) {
                const float* base = B8 + (ch + 1) * 81 + j;
#pragma unroll
                for (int i = 0; i < NCLS; ++i) nb[i] = base[i * NCLS];
            }

            const float p0 = __shfl_sync(0xffffffffu, p, 0);
            const float p1 = __shfl_sync(0xffffffffu, p, 1);
            const float p2 = __shfl_sync(0xffffffffu, p, 2);
            const float p3 = __shfl_sync(0xffffffffu, p, 3);
            const float p4 = __shfl_sync(0xffffffffu, p, 4);
            const float p5 = __shfl_sync(0xffffffffu, p, 5);
            const float p6 = __shfl_sync(0xffffffffu, p, 6);
            const float p7 = __shfl_sync(0xffffffffu, p, 7);
            const float p8 = __shfl_sync(0xffffffffu, p, 8);

            const float s0 = fmaf(p2, bcol[2], fmaf(p1, bcol[1], p0 * bcol[0]));
            const float s1 = fmaf(p5, bcol[5], fmaf(p4, bcol[4], p3 * bcol[3]));
            const float s2 = fmaf(p8, bcol[8], fmaf(p7, bcol[7], p6 * bcol[6]));
            float pn = (s0 + s1) + s2;

            if (ch & 1) {
                const float sv = __shfl_sync(0xffffffffu, pn, 0);
                pn *= __frcp_rn(sv);
                clog += __logf(sv);
            }
            p = pn;
#pragma unroll
            for (int i = 0; i < NCLS; ++i) bcol[i] = nb[i];
        }

        float v = (lane < NCLS) ? p * __expf(enS[j]) : 0.f;
#pragma unroll
        for (int off = 16; off; off >>= 1)
            v += __shfl_xor_sync(0xffffffffu, v, off);
        if (lane == 0) den_sh = clog + __logf(v);
    }
    else if (warp == 1) {
        float sc = 0.f;
        int   cnt = 0;
        for (int t = lane; t < SEQ; t += 32) {
            const int mt = mS[t];
            cnt += mt;
            if (t >= 1 && mt) {
                const int cur = tagS[t];
                const int prv = tagS[t - 1];
                sc += lgb[t * NCLS + cur] + trS[prv * NCLS + cur];
            }
        }
#pragma unroll
        for (int off = 16; off; off >>= 1) {
            sc  += __shfl_xor_sync(0xffffffffu, sc,  off);
            cnt += __shfl_xor_sync(0xffffffffu, cnt, off);
        }
        if (lane == 0) {
            const int first = tagS[0];
            sc += stS[first] + lgb[first];
            sc += enS[tagS[cnt - 1]];
            num_sh = sc;
        }
    }

    __syncthreads();

    // ---- Phase D: publish llh; last finished block reduces ----
    if (tid == 0) {
        g_llh[b] = num_sh - den_sh;
        __threadfence();
        const int old = atomicAdd(&g_done, 1);
        isLast = (old == BATCH - 1) ? 1 : 0;
    }
    __syncthreads();

    if (isLast) {
        if (tid < 128) {
            float v = g_llh[tid];
#pragma unroll
            for (int off = 16; off; off >>= 1)
                v += __shfl_xor_sync(0xffffffffu, v, off);
            if (lane == 0) ws[warp] = v;
        }
        __syncthreads();
        if (tid == 0) {
            const float tot = (ws[0] + ws[1]) + (ws[2] + ws[3]);
            out[0] = -tot / (float)BATCH;
            g_done = 0;   // reset for next graph replay
        }
    }
}

extern "C" void kernel_launch(void* const* d_in, const int* in_sizes, int n_in,
                              void* d_out, int out_size)
{
    const float4* feat4  = (const float4*)d_in[0];
    const int*    labels = (const int*)d_in[1];
    const int*    mask   = (const int*)d_in[2];
    const float*  W      = (const float*)d_in[3];
    const float*  bias   = (const float*)d_in[4];
    const float*  st     = (const float*)d_in[5];
    const float*  en     = (const float*)d_in[6];
    const float*  tr     = (const float*)d_in[7];

    float* out    = (float*)d_out;
    float* logits = out + 1;

    gemm_kernel<<<ROWS / 64, 256>>>(feat4, W, bias, logits);
    crf_kernel<<<BATCH, 768>>>(logits, labels, mask, st, en, tr, out);
}